// round 1
// baseline (speedup 1.0000x reference)
#include <cuda_runtime.h>
#include <cstdint>

// ---------------- model constants ----------------
#define BB 16
#define N0 512
#define N1 256
#define N2 128
#define F0 64
#define F1 128
#define F2 256
#define KK 8
#define FC_OUT 512
#define FLATD (N2 * F2)        // 32768
#define EPSC 1e-9f

// ---------------- scratch (device globals, no allocs) ----------------
__device__ float g_u0[BB * N0 * KK];
__device__ float g_w0[BB * N0 * KK];
__device__ float g_X0[BB * N0 * (F0 + KK * F0)];   // [8192, 576]
__device__ float g_H0[BB * N0 * F1];
__device__ float g_H0p[BB * N1 * F1];
__device__ float g_C1[BB * N1 * 3];
__device__ float g_u1[BB * N1 * KK];
__device__ float g_w1[BB * N1 * KK];
__device__ float g_X1[BB * N1 * (F1 + KK * F1)];   // [4096, 1152]
__device__ float g_H1[BB * N1 * F2];
__device__ float g_Flat[BB * N2 * F2];             // [16, 32768]
__device__ float g_part[32][BB * FC_OUT];          // split-K FC partials

// ---------------- gates: u = softplus(V@gkw+b), w = sigmoid(V@acw+b) ----------------
template <int F>
__global__ void uw_kernel(const float* __restrict__ V,
                          const float* __restrict__ gkw, const float* __restrict__ gkb,
                          const float* __restrict__ acw, const float* __restrict__ acb,
                          float* __restrict__ u, float* __restrict__ w, int BN) {
    int idx = blockIdx.x * blockDim.x + threadIdx.x;
    if (idx >= BN * KK) return;
    int row = idx >> 3, k = idx & 7;
    const float* v = V + (size_t)row * F;
    float su = gkb[k], sw = acb[k];
#pragma unroll 8
    for (int f = 0; f < F; ++f) {
        float vv = v[f];
        su += vv * gkw[f * KK + k];
        sw += vv * acw[f * KK + k];
    }
    u[idx] = fmaxf(su, 0.f) + log1pf(__expf(-fabsf(su)));   // stable softplus
    w[idx] = 1.f / (1.f + __expf(-sw));
}

// ---------------- fused message passing ----------------
// Computes X[b,i, 0:F] = V[b,i,:]  and  X[b,i, F + k*F + f] = sum_j A[b,k,i,j] * V[b,j,f]
// A built on the fly from coords + gates, tile-cached in smem.
template <int F, int TI, int TJ>
__global__ __launch_bounds__(256) void msg_kernel(
        const float* __restrict__ V, const float* __restrict__ C,
        const float* __restrict__ u, const float* __restrict__ w,
        float* __restrict__ X, int N) {
    constexpr int XW = F + KK * F;
    constexpr int FG = 256 / TI;   // f-groups
    constexpr int FPT = F / FG;    // floats per thread along f

    const int b = blockIdx.y;
    const int i0 = blockIdx.x * TI;
    const int tid = threadIdx.x;

    __shared__ float4 sCi[TI];
    __shared__ float  sRni[TI];
    __shared__ float  sU[TI][KK];
    __shared__ float  sW[TI][KK];
    __shared__ float4 sCj[TJ];
    __shared__ float  sRnj[TJ];
    __shared__ float  sVj[TJ][F];
    __shared__ float  sA[TI][TJ][KK];

    // row-side statics
    if (tid < TI) {
        int i = i0 + tid;
        float x = C[((size_t)b * N + i) * 3 + 0];
        float y = C[((size_t)b * N + i) * 3 + 1];
        float z = C[((size_t)b * N + i) * 3 + 2];
        float l2 = x * x + y * y + z * z;
        sCi[tid] = make_float4(x, y, z, l2);
        sRni[tid] = rsqrtf(l2 + EPSC);
    }
    if (tid < TI * KK) {
        int i = tid / KK, k = tid & 7;
        sU[i][k] = u[((size_t)b * N + i0 + i) * KK + k];
        sW[i][k] = w[((size_t)b * N + i0 + i) * KK + k];
    }

    // copy V rows into the first F columns of X
    for (int t = tid; t < TI * (F / 4); t += 256) {
        int i = t / (F / 4), fq = t % (F / 4);
        float4 vv = reinterpret_cast<const float4*>(V + ((size_t)b * N + i0 + i) * F)[fq];
        reinterpret_cast<float4*>(X + ((size_t)b * N + i0 + i) * XW)[fq] = vv;
    }

    float acc[KK][FPT];
#pragma unroll
    for (int k = 0; k < KK; ++k)
#pragma unroll
        for (int f = 0; f < FPT; ++f) acc[k][f] = 0.f;

    const int il = tid / FG;
    const int fg = tid % FG;

    for (int j0 = 0; j0 < N; j0 += TJ) {
        __syncthreads();   // previous tile readers done
        if (tid < TJ) {
            int j = j0 + tid;
            float x = C[((size_t)b * N + j) * 3 + 0];
            float y = C[((size_t)b * N + j) * 3 + 1];
            float z = C[((size_t)b * N + j) * 3 + 2];
            float l2 = x * x + y * y + z * z;
            sCj[tid] = make_float4(x, y, z, l2);
            sRnj[tid] = rsqrtf(l2 + EPSC);
        }
        for (int t = tid; t < TJ * (F / 4); t += 256) {
            int j = t / (F / 4), fq = t % (F / 4);
            reinterpret_cast<float4*>(&sVj[j][0])[fq] =
                reinterpret_cast<const float4*>(V + ((size_t)b * N + j0 + j) * F)[fq];
        }
        __syncthreads();
        // build A tile (one exp per (i,j,k))
        for (int p = tid; p < TI * TJ; p += 256) {
            int i = p / TJ, j = p % TJ;
            float4 ci = sCi[i], cj = sCj[j];
            float dot = ci.x * cj.x + ci.y * cj.y + ci.z * cj.z;
            float d2 = fabsf(ci.w + cj.w - 2.f * dot) + EPSC;   // == D^2 (ref: sqrt then square)
            float cs = dot * sRni[i] * sRnj[j];
#pragma unroll
            for (int k = 0; k < KK; ++k) {
                float e = __expf(-d2 * sU[i][k]);
                float wk = sW[i][k];
                sA[i][j][k] = e * (wk * cs + 1.f - wk);
            }
        }
        __syncthreads();
        // accumulate M += A * Vj
#pragma unroll 2
        for (int jj = 0; jj < TJ; ++jj) {
            float4 a0 = reinterpret_cast<float4*>(&sA[il][jj][0])[0];
            float4 a1 = reinterpret_cast<float4*>(&sA[il][jj][0])[1];
            float av[KK] = {a0.x, a0.y, a0.z, a0.w, a1.x, a1.y, a1.z, a1.w};
            float vv[FPT];
#pragma unroll
            for (int q = 0; q < FPT / 4; ++q) {
                float4 t4 = reinterpret_cast<float4*>(&sVj[jj][fg * FPT])[q];
                vv[q * 4 + 0] = t4.x; vv[q * 4 + 1] = t4.y;
                vv[q * 4 + 2] = t4.z; vv[q * 4 + 3] = t4.w;
            }
#pragma unroll
            for (int k = 0; k < KK; ++k)
#pragma unroll
                for (int f = 0; f < FPT; ++f) acc[k][f] += av[k] * vv[f];
        }
    }

    // write M section of X
    float* xrow = X + ((size_t)b * N + i0 + il) * XW + F;
#pragma unroll
    for (int k = 0; k < KK; ++k) {
#pragma unroll
        for (int q = 0; q < FPT / 4; ++q) {
            float4 o;
            o.x = acc[k][q * 4 + 0]; o.y = acc[k][q * 4 + 1];
            o.z = acc[k][q * 4 + 2]; o.w = acc[k][q * 4 + 3];
            reinterpret_cast<float4*>(xrow + k * F + fg * FPT)[q] = o;
        }
    }
}

// ---------------- tiled GEMM + tanh + BN affine ----------------
// H[m,n] = bng[n] * tanh( sum_k A[m,k]*Wt[k,n] + bias[n] ) + bnb[n]
__global__ __launch_bounds__(256) void gemm_tanh_bn(
        const float* __restrict__ A, const float* __restrict__ Wt,
        const float* __restrict__ bias, const float* __restrict__ bng,
        const float* __restrict__ bnb, float* __restrict__ Hout,
        int Mrows, int Kdim, int Ncols) {
    constexpr int BM = 64, BN = 64, BK = 16;
    __shared__ float As[BK][BM + 4];
    __shared__ float Bs[BK][BN];
    const int bm = blockIdx.y * BM, bn = blockIdx.x * BN;
    const int tid = threadIdx.x;
    const int tx = tid % 16, ty = tid / 16;
    float acc[4][4];
#pragma unroll
    for (int m = 0; m < 4; ++m)
#pragma unroll
        for (int n = 0; n < 4; ++n) acc[m][n] = 0.f;

    for (int k0 = 0; k0 < Kdim; k0 += BK) {
        {   // A tile: 64x16, transposed into smem
            int r = tid / 4, kq = tid % 4;
            float4 a4 = *reinterpret_cast<const float4*>(A + (size_t)(bm + r) * Kdim + k0 + kq * 4);
            As[kq * 4 + 0][r] = a4.x; As[kq * 4 + 1][r] = a4.y;
            As[kq * 4 + 2][r] = a4.z; As[kq * 4 + 3][r] = a4.w;
        }
        {   // B tile: 16x64
            int kr = tid / 16, cq = tid % 16;
            float4 b4 = *reinterpret_cast<const float4*>(Wt + (size_t)(k0 + kr) * Ncols + bn + cq * 4);
            *reinterpret_cast<float4*>(&Bs[kr][cq * 4]) = b4;
        }
        __syncthreads();
#pragma unroll
        for (int kk = 0; kk < BK; ++kk) {
            float4 a4 = *reinterpret_cast<float4*>(&As[kk][ty * 4]);
            float4 b4 = *reinterpret_cast<float4*>(&Bs[kk][tx * 4]);
            float am[4] = {a4.x, a4.y, a4.z, a4.w};
            float bv[4] = {b4.x, b4.y, b4.z, b4.w};
#pragma unroll
            for (int m = 0; m < 4; ++m)
#pragma unroll
                for (int n = 0; n < 4; ++n) acc[m][n] += am[m] * bv[n];
        }
        __syncthreads();
    }
#pragma unroll
    for (int m = 0; m < 4; ++m) {
        int row = bm + ty * 4 + m;
        int col0 = bn + tx * 4;
        float4 o;
        float h0 = tanhf(acc[m][0] + bias[col0 + 0]);
        float h1 = tanhf(acc[m][1] + bias[col0 + 1]);
        float h2 = tanhf(acc[m][2] + bias[col0 + 2]);
        float h3 = tanhf(acc[m][3] + bias[col0 + 3]);
        o.x = bng[col0 + 0] * h0 + bnb[col0 + 0];
        o.y = bng[col0 + 1] * h1 + bnb[col0 + 1];
        o.z = bng[col0 + 2] * h2 + bnb[col0 + 2];
        o.w = bng[col0 + 3] * h3 + bnb[col0 + 3];
        *reinterpret_cast<float4*>(Hout + (size_t)row * Ncols + col0) = o;
    }
}

// ---------------- average pool over consecutive node pairs ----------------
__global__ void pool_kernel(const float* __restrict__ in, float* __restrict__ out,
                            int Nout, int F, int total) {
    int idx = blockIdx.x * blockDim.x + threadIdx.x;
    if (idx >= total) return;
    int f = idx % F;
    int rest = idx / F;
    int i = rest % Nout;
    int b = rest / Nout;
    size_t base = ((size_t)b * (Nout * 2) + 2 * i) * F + f;
    out[idx] = 0.5f * (in[base] + in[base + F]);
}

// ---------------- FC: split-K partial sums (deterministic) ----------------
__global__ __launch_bounds__(128) void fc_partial(const float* __restrict__ Flat,
                                                  const float* __restrict__ W) {
    constexpr int KCHUNK = FLATD / 32;   // 1024
    const int col = blockIdx.x * 128 + threadIdx.x;
    const int kbase = blockIdx.y * KCHUNK;
    __shared__ float sF[BB][128];
    float acc[BB];
#pragma unroll
    for (int b = 0; b < BB; ++b) acc[b] = 0.f;

    for (int k0 = 0; k0 < KCHUNK; k0 += 128) {
        __syncthreads();
        for (int t = threadIdx.x; t < BB * 128; t += 128) {
            int b = t / 128, kk = t % 128;
            sF[b][kk] = Flat[(size_t)b * FLATD + kbase + k0 + kk];
        }
        __syncthreads();
#pragma unroll 4
        for (int kk = 0; kk < 128; ++kk) {
            float wv = W[(size_t)(kbase + k0 + kk) * FC_OUT + col];
#pragma unroll
            for (int b = 0; b < BB; ++b) acc[b] += sF[b][kk] * wv;
        }
    }
#pragma unroll
    for (int b = 0; b < BB; ++b) g_part[blockIdx.y][b * FC_OUT + col] = acc[b];
}

__global__ void fc_finalize(const float* __restrict__ fcb, float* __restrict__ out) {
    int idx = blockIdx.x * blockDim.x + threadIdx.x;
    if (idx >= BB * FC_OUT) return;
    int col = idx % FC_OUT;
    float s = fcb[col];
#pragma unroll
    for (int t = 0; t < 32; ++t) s += g_part[t][idx];
    out[idx] = 1.f / (1.f + __expf(-s));
}

// ---------------- launch ----------------
extern "C" void kernel_launch(void* const* d_in, const int* in_sizes, int n_in,
                              void* d_out, int out_size) {
    const float* V    = (const float*)d_in[0];
    const float* C    = (const float*)d_in[1];
    const float* gkw0 = (const float*)d_in[2];
    const float* gkb0 = (const float*)d_in[3];
    const float* acw0 = (const float*)d_in[4];
    const float* acb0 = (const float*)d_in[5];
    const float* gcw0 = (const float*)d_in[6];
    const float* gcb0 = (const float*)d_in[7];
    const float* bng0 = (const float*)d_in[8];
    const float* bnb0 = (const float*)d_in[9];
    const float* gkw1 = (const float*)d_in[10];
    const float* gkb1 = (const float*)d_in[11];
    const float* acw1 = (const float*)d_in[12];
    const float* acb1 = (const float*)d_in[13];
    const float* gcw1 = (const float*)d_in[14];
    const float* gcb1 = (const float*)d_in[15];
    const float* bng1 = (const float*)d_in[16];
    const float* bnb1 = (const float*)d_in[17];
    const float* fcw  = (const float*)d_in[18];
    const float* fcb  = (const float*)d_in[19];
    float* out = (float*)d_out;

    float *u0, *w0, *X0, *H0, *H0p, *C1, *u1, *w1, *X1, *H1, *Flat;
    cudaGetSymbolAddress((void**)&u0, g_u0);
    cudaGetSymbolAddress((void**)&w0, g_w0);
    cudaGetSymbolAddress((void**)&X0, g_X0);
    cudaGetSymbolAddress((void**)&H0, g_H0);
    cudaGetSymbolAddress((void**)&H0p, g_H0p);
    cudaGetSymbolAddress((void**)&C1, g_C1);
    cudaGetSymbolAddress((void**)&u1, g_u1);
    cudaGetSymbolAddress((void**)&w1, g_w1);
    cudaGetSymbolAddress((void**)&X1, g_X1);
    cudaGetSymbolAddress((void**)&H1, g_H1);
    cudaGetSymbolAddress((void**)&Flat, g_Flat);

    // layer 0
    uw_kernel<F0><<<(BB * N0 * KK + 255) / 256, 256>>>(V, gkw0, gkb0, acw0, acb0, u0, w0, BB * N0);
    msg_kernel<F0, 16, 32><<<dim3(N0 / 16, BB), 256>>>(V, C, u0, w0, X0, N0);
    gemm_tanh_bn<<<dim3(F1 / 64, BB * N0 / 64), 256>>>(X0, gcw0, gcb0, bng0, bnb0, H0,
                                                       BB * N0, (KK + 1) * F0, F1);
    // pool -> layer1 inputs
    pool_kernel<<<(BB * N1 * F1 + 255) / 256, 256>>>(H0, H0p, N1, F1, BB * N1 * F1);
    pool_kernel<<<(BB * N1 * 3 + 255) / 256, 256>>>(C, C1, N1, 3, BB * N1 * 3);

    // layer 1
    uw_kernel<F1><<<(BB * N1 * KK + 255) / 256, 256>>>(H0p, gkw1, gkb1, acw1, acb1, u1, w1, BB * N1);
    msg_kernel<F1, 16, 32><<<dim3(N1 / 16, BB), 256>>>(H0p, C1, u1, w1, X1, N1);
    gemm_tanh_bn<<<dim3(F2 / 64, BB * N1 / 64), 256>>>(X1, gcw1, gcb1, bng1, bnb1, H1,
                                                       BB * N1, (KK + 1) * F1, F2);
    // pool -> flat
    pool_kernel<<<(BB * N2 * F2 + 255) / 256, 256>>>(H1, Flat, N2, F2, BB * N2 * F2);

    // FC head
    fc_partial<<<dim3(FC_OUT / 128, 32), 128>>>(Flat, fcw);
    fc_finalize<<<(BB * FC_OUT + 255) / 256, 256>>>(fcb, out);
}

// round 2
// speedup vs baseline: 1.3500x; 1.3500x over previous
#include <cuda_runtime.h>
#include <cstdint>

// ---------------- model constants ----------------
#define BB 16
#define N0 512
#define N1 256
#define N2 128
#define F0c 64
#define F1c 128
#define F2c 256
#define KK 8
#define FC_OUT 512
#define FLATD (N2 * F2c)        // 32768
#define EPSC 1e-9f

// ---------------- scratch (device globals, no allocs) ----------------
__device__ float g_X0[BB * N0 * (F0c + KK * F0c)];   // [8192, 576]
__device__ float g_H0p[BB * N1 * F1c];               // pooled layer-0 output
__device__ float g_C1[BB * N1 * 3];
__device__ float g_X1[BB * N1 * (F1c + KK * F1c)];   // [4096, 1152]
__device__ float g_Flat[BB * N2 * F2c];              // pooled layer-1 output = FC input
__device__ float g_part[64][BB * FC_OUT];            // split-K FC partials

// =================================================================
// Fused message passing (+ gates in prologue)
//   u = softplus(V@gkw+gkb), w = sigmoid(V@acw+acb)   (rows of this tile only)
//   X[b,i,0:F] = V[b,i,:]
//   X[b,i,F+k*F+f] = sum_j exp(-D2*u_ik) * (w_ik*cos_ij + 1-w_ik) * V[b,j,f]
// =================================================================
template <int F, int TI, int TJ>
struct MsgSmem {
    float4 Ci[TI];
    float  Rni[TI];
    float  U[TI][KK];
    float  W[TI][KK];
    float4 Cj[TJ];
    float  Rnj[TJ];
    float  Vj[TJ][F];
    float  A[TI][TJ][KK];
};

template <int F, int TI, int TJ>
__global__ __launch_bounds__(256) void msg_kernel(
        const float* __restrict__ V, const float* __restrict__ C,
        const float* __restrict__ gkw, const float* __restrict__ gkb,
        const float* __restrict__ acw, const float* __restrict__ acb,
        float* __restrict__ X, int N) {
    constexpr int XW = F + KK * F;
    constexpr int FG = 256 / TI;   // f-groups (16)
    constexpr int FPT = F / FG;    // floats per thread along f

    extern __shared__ char smem_raw[];
    auto& S = *reinterpret_cast<MsgSmem<F, TI, TJ>*>(smem_raw);

    const int b = blockIdx.y;
    const int i0 = blockIdx.x * TI;
    const int tid = threadIdx.x;

    // row-side coords
    if (tid < TI) {
        int i = i0 + tid;
        float x = C[((size_t)b * N + i) * 3 + 0];
        float y = C[((size_t)b * N + i) * 3 + 1];
        float z = C[((size_t)b * N + i) * 3 + 2];
        float l2 = x * x + y * y + z * z;
        S.Ci[tid] = make_float4(x, y, z, l2);
        S.Rni[tid] = rsqrtf(l2 + EPSC);
    }
    // fused gates: exactly TI*KK*2 == 256 threads
    {
        int gate = tid >> 7;           // 0 = u (softplus), 1 = w (sigmoid)
        int r = (tid >> 3) & (TI - 1);
        int k = tid & 7;
        const float* wgt = gate ? acw : gkw;
        float s = gate ? acb[k] : gkb[k];
        const float* vrow = V + ((size_t)b * N + i0 + r) * F;
#pragma unroll 8
        for (int f = 0; f < F; ++f) s += vrow[f] * wgt[f * KK + k];
        if (gate) S.W[r][k] = 1.f / (1.f + __expf(-s));
        else      S.U[r][k] = fmaxf(s, 0.f) + log1pf(__expf(-fabsf(s)));
    }
    // copy V rows into the first F columns of X
    for (int t = tid; t < TI * (F / 4); t += 256) {
        int i = t / (F / 4), fq = t % (F / 4);
        float4 vv = reinterpret_cast<const float4*>(V + ((size_t)b * N + i0 + i) * F)[fq];
        reinterpret_cast<float4*>(X + ((size_t)b * N + i0 + i) * XW)[fq] = vv;
    }

    float acc[KK][FPT];
#pragma unroll
    for (int k = 0; k < KK; ++k)
#pragma unroll
        for (int f = 0; f < FPT; ++f) acc[k][f] = 0.f;

    const int il = tid / FG;
    const int fg = tid % FG;

    for (int j0 = 0; j0 < N; j0 += TJ) {
        __syncthreads();   // previous tile readers done (also covers prologue)
        if (tid < TJ) {
            int j = j0 + tid;
            float x = C[((size_t)b * N + j) * 3 + 0];
            float y = C[((size_t)b * N + j) * 3 + 1];
            float z = C[((size_t)b * N + j) * 3 + 2];
            float l2 = x * x + y * y + z * z;
            S.Cj[tid] = make_float4(x, y, z, l2);
            S.Rnj[tid] = rsqrtf(l2 + EPSC);
        }
        for (int t = tid; t < TJ * (F / 4); t += 256) {
            int j = t / (F / 4), fq = t % (F / 4);
            reinterpret_cast<float4*>(&S.Vj[j][0])[fq] =
                reinterpret_cast<const float4*>(V + ((size_t)b * N + j0 + j) * F)[fq];
        }
        __syncthreads();
        // build A tile
#pragma unroll
        for (int s = 0; s < (TI * TJ) / 256; ++s) {
            int p = tid + s * 256;
            int i = p / TJ, j = p % TJ;
            float4 ci = S.Ci[i], cj = S.Cj[j];
            float dot = ci.x * cj.x + ci.y * cj.y + ci.z * cj.z;
            float d2 = fabsf(ci.w + cj.w - 2.f * dot) + EPSC;   // == D^2
            float cs = dot * S.Rni[i] * S.Rnj[j];
            float4 e0, e1;
            {
                float v[8];
#pragma unroll
                for (int k = 0; k < KK; ++k) {
                    float e = __expf(-d2 * S.U[i][k]);
                    float wk = S.W[i][k];
                    v[k] = e * (wk * cs + 1.f - wk);
                }
                e0 = make_float4(v[0], v[1], v[2], v[3]);
                e1 = make_float4(v[4], v[5], v[6], v[7]);
            }
            reinterpret_cast<float4*>(&S.A[i][j][0])[0] = e0;
            reinterpret_cast<float4*>(&S.A[i][j][0])[1] = e1;
        }
        __syncthreads();
        // accumulate M += A * Vj
#pragma unroll 4
        for (int jj = 0; jj < TJ; ++jj) {
            float4 a0 = reinterpret_cast<float4*>(&S.A[il][jj][0])[0];
            float4 a1 = reinterpret_cast<float4*>(&S.A[il][jj][0])[1];
            float av[KK] = {a0.x, a0.y, a0.z, a0.w, a1.x, a1.y, a1.z, a1.w};
            float vv[FPT];
#pragma unroll
            for (int q = 0; q < FPT / 4; ++q) {
                float4 t4 = reinterpret_cast<float4*>(&S.Vj[jj][fg * FPT])[q];
                vv[q * 4 + 0] = t4.x; vv[q * 4 + 1] = t4.y;
                vv[q * 4 + 2] = t4.z; vv[q * 4 + 3] = t4.w;
            }
#pragma unroll
            for (int k = 0; k < KK; ++k)
#pragma unroll
                for (int f = 0; f < FPT; ++f) acc[k][f] += av[k] * vv[f];
        }
    }

    // write M section of X
    float* xrow = X + ((size_t)b * N + i0 + il) * XW + F;
#pragma unroll
    for (int k = 0; k < KK; ++k) {
#pragma unroll
        for (int q = 0; q < FPT / 4; ++q) {
            float4 o;
            o.x = acc[k][q * 4 + 0]; o.y = acc[k][q * 4 + 1];
            o.z = acc[k][q * 4 + 2]; o.w = acc[k][q * 4 + 3];
            reinterpret_cast<float4*>(xrow + k * F + fg * FPT)[q] = o;
        }
    }
}

// =================================================================
// GEMM + tanh + BN affine + fused 2:1 row pooling
//   pooled_out[pr, n] = 0.5 * sum_{m in pair} ( bng[n]*tanh(A@Wt + bias) + bnb[n] )
//   128x64 tile, 8x4/thread, double-buffered smem (1 sync / k-tile)
// =================================================================
template <int NIN>
__global__ __launch_bounds__(256) void gemm_pool(
        const float* __restrict__ A, const float* __restrict__ Wt,
        const float* __restrict__ bias, const float* __restrict__ bng,
        const float* __restrict__ bnb, float* __restrict__ Out,
        int Kd, int Nc) {
    constexpr int BM = 128, BN = 64, BK = 16;
    __shared__ float As[2][BK][BM + 4];
    __shared__ float Bs[2][BK][BN];
    const int bm = blockIdx.y * BM, bn = blockIdx.x * BN;
    const int tid = threadIdx.x;
    const int tx = tid & 15, ty = tid >> 4;

    const int ar = tid >> 2, akq = tid & 3;    // A loader: rows ar, ar+64
    const int bkr = tid >> 4, bcq = tid & 15;  // B loader

    float acc[8][4];
#pragma unroll
    for (int m = 0; m < 8; ++m)
#pragma unroll
        for (int n = 0; n < 4; ++n) acc[m][n] = 0.f;

    float4 ra0, ra1, rb;
    const int nk = Kd / BK;

    // prefetch tile 0
    {
        ra0 = *reinterpret_cast<const float4*>(A + (size_t)(bm + ar) * Kd + akq * 4);
        ra1 = *reinterpret_cast<const float4*>(A + (size_t)(bm + 64 + ar) * Kd + akq * 4);
        rb  = *reinterpret_cast<const float4*>(Wt + (size_t)bkr * Nc + bn + bcq * 4);
        As[0][akq * 4 + 0][ar] = ra0.x; As[0][akq * 4 + 1][ar] = ra0.y;
        As[0][akq * 4 + 2][ar] = ra0.z; As[0][akq * 4 + 3][ar] = ra0.w;
        As[0][akq * 4 + 0][64 + ar] = ra1.x; As[0][akq * 4 + 1][64 + ar] = ra1.y;
        As[0][akq * 4 + 2][64 + ar] = ra1.z; As[0][akq * 4 + 3][64 + ar] = ra1.w;
        *reinterpret_cast<float4*>(&Bs[0][bkr][bcq * 4]) = rb;
    }
    __syncthreads();

    for (int kt = 0; kt < nk; ++kt) {
        const int buf = kt & 1;
        if (kt + 1 < nk) {
            int k0 = (kt + 1) * BK;
            ra0 = *reinterpret_cast<const float4*>(A + (size_t)(bm + ar) * Kd + k0 + akq * 4);
            ra1 = *reinterpret_cast<const float4*>(A + (size_t)(bm + 64 + ar) * Kd + k0 + akq * 4);
            rb  = *reinterpret_cast<const float4*>(Wt + (size_t)(k0 + bkr) * Nc + bn + bcq * 4);
        }
#pragma unroll
        for (int kk = 0; kk < BK; ++kk) {
            float4 a0 = *reinterpret_cast<float4*>(&As[buf][kk][ty * 8]);
            float4 a1 = *reinterpret_cast<float4*>(&As[buf][kk][ty * 8 + 4]);
            float4 bv = *reinterpret_cast<float4*>(&Bs[buf][kk][tx * 4]);
            float am[8] = {a0.x, a0.y, a0.z, a0.w, a1.x, a1.y, a1.z, a1.w};
            float bb[4] = {bv.x, bv.y, bv.z, bv.w};
#pragma unroll
            for (int m = 0; m < 8; ++m)
#pragma unroll
                for (int n = 0; n < 4; ++n) acc[m][n] += am[m] * bb[n];
        }
        if (kt + 1 < nk) {
            const int nb = 1 - buf;
            As[nb][akq * 4 + 0][ar] = ra0.x; As[nb][akq * 4 + 1][ar] = ra0.y;
            As[nb][akq * 4 + 2][ar] = ra0.z; As[nb][akq * 4 + 3][ar] = ra0.w;
            As[nb][akq * 4 + 0][64 + ar] = ra1.x; As[nb][akq * 4 + 1][64 + ar] = ra1.y;
            As[nb][akq * 4 + 2][64 + ar] = ra1.z; As[nb][akq * 4 + 3][64 + ar] = ra1.w;
            *reinterpret_cast<float4*>(&Bs[nb][bkr][bcq * 4]) = rb;
            __syncthreads();
        }
    }

    // epilogue: tanh + BN affine + pool consecutive row pairs
    float4 bi = *reinterpret_cast<const float4*>(bias + bn + tx * 4);
    float4 gg = *reinterpret_cast<const float4*>(bng + bn + tx * 4);
    float4 be = *reinterpret_cast<const float4*>(bnb + bn + tx * 4);
#pragma unroll
    for (int mm = 0; mm < 8; mm += 2) {
        int m0 = bm + ty * 8 + mm;
        int pr = (m0 / NIN) * (NIN / 2) + (m0 % NIN) / 2;
        float4 o;
        o.x = gg.x * 0.5f * (tanhf(acc[mm][0] + bi.x) + tanhf(acc[mm + 1][0] + bi.x)) + be.x;
        o.y = gg.y * 0.5f * (tanhf(acc[mm][1] + bi.y) + tanhf(acc[mm + 1][1] + bi.y)) + be.y;
        o.z = gg.z * 0.5f * (tanhf(acc[mm][2] + bi.z) + tanhf(acc[mm + 1][2] + bi.z)) + be.z;
        o.w = gg.w * 0.5f * (tanhf(acc[mm][3] + bi.w) + tanhf(acc[mm + 1][3] + bi.w)) + be.w;
        *reinterpret_cast<float4*>(Out + (size_t)pr * Nc + bn + tx * 4) = o;
    }
}

// ---------------- coord pooling (tiny) ----------------
__global__ void poolC_kernel(const float* __restrict__ C, float* __restrict__ C1) {
    int idx = blockIdx.x * blockDim.x + threadIdx.x;
    if (idx >= BB * N1 * 3) return;
    int c = idx % 3;
    int i = (idx / 3) % N1;
    int b = idx / (3 * N1);
    size_t base = ((size_t)b * N0 + 2 * i) * 3 + c;
    C1[idx] = 0.5f * (C[base] + C[base + 3]);
}

// ---------------- FC: split-K partials (deterministic) ----------------
__global__ __launch_bounds__(128) void fc_partial(const float* __restrict__ Flat,
                                                  const float* __restrict__ W) {
    constexpr int KCH = FLATD / 64;   // 512
    const int kb = blockIdx.x * KCH;
    const int tid = threadIdx.x;
    __shared__ float sF[BB][KCH];     // 32KB
    for (int t = tid; t < BB * KCH / 4; t += 128) {
        int b = t / (KCH / 4), kq = t % (KCH / 4);
        *reinterpret_cast<float4*>(&sF[b][kq * 4]) =
            *reinterpret_cast<const float4*>(Flat + (size_t)b * FLATD + kb + kq * 4);
    }
    __syncthreads();

    float4 acc[BB];
#pragma unroll
    for (int b = 0; b < BB; ++b) acc[b] = make_float4(0.f, 0.f, 0.f, 0.f);

    const float* wp = W + (size_t)kb * FC_OUT + tid * 4;
    for (int k = 0; k < KCH; k += 4) {
        float4 w0 = *reinterpret_cast<const float4*>(wp + (size_t)(k + 0) * FC_OUT);
        float4 w1 = *reinterpret_cast<const float4*>(wp + (size_t)(k + 1) * FC_OUT);
        float4 w2 = *reinterpret_cast<const float4*>(wp + (size_t)(k + 2) * FC_OUT);
        float4 w3 = *reinterpret_cast<const float4*>(wp + (size_t)(k + 3) * FC_OUT);
#pragma unroll
        for (int b = 0; b < BB; ++b) {
            float4 f = *reinterpret_cast<float4*>(&sF[b][k]);
            acc[b].x += f.x * w0.x + f.y * w1.x + f.z * w2.x + f.w * w3.x;
            acc[b].y += f.x * w0.y + f.y * w1.y + f.z * w2.y + f.w * w3.y;
            acc[b].z += f.x * w0.z + f.y * w1.z + f.z * w2.z + f.w * w3.z;
            acc[b].w += f.x * w0.w + f.y * w1.w + f.z * w2.w + f.w * w3.w;
        }
    }
#pragma unroll
    for (int b = 0; b < BB; ++b)
        *reinterpret_cast<float4*>(&g_part[blockIdx.x][b * FC_OUT + tid * 4]) = acc[b];
}

__global__ void fc_finalize(const float* __restrict__ fcb, float* __restrict__ out) {
    int idx = blockIdx.x * blockDim.x + threadIdx.x;
    if (idx >= BB * FC_OUT) return;
    int col = idx & (FC_OUT - 1);
    float s = fcb[col];
#pragma unroll
    for (int t = 0; t < 64; ++t) s += g_part[t][idx];
    out[idx] = 1.f / (1.f + __expf(-s));
}

// ---------------- launch ----------------
extern "C" void kernel_launch(void* const* d_in, const int* in_sizes, int n_in,
                              void* d_out, int out_size) {
    const float* V    = (const float*)d_in[0];
    const float* C    = (const float*)d_in[1];
    const float* gkw0 = (const float*)d_in[2];
    const float* gkb0 = (const float*)d_in[3];
    const float* acw0 = (const float*)d_in[4];
    const float* acb0 = (const float*)d_in[5];
    const float* gcw0 = (const float*)d_in[6];
    const float* gcb0 = (const float*)d_in[7];
    const float* bng0 = (const float*)d_in[8];
    const float* bnb0 = (const float*)d_in[9];
    const float* gkw1 = (const float*)d_in[10];
    const float* gkb1 = (const float*)d_in[11];
    const float* acw1 = (const float*)d_in[12];
    const float* acb1 = (const float*)d_in[13];
    const float* gcw1 = (const float*)d_in[14];
    const float* gcb1 = (const float*)d_in[15];
    const float* gcw1b= (const float*)d_in[15];
    const float* bng1 = (const float*)d_in[16];
    const float* bnb1 = (const float*)d_in[17];
    const float* fcw  = (const float*)d_in[18];
    const float* fcb  = (const float*)d_in[19];
    (void)gcw1b;
    float* out = (float*)d_out;

    float *X0, *H0p, *C1, *X1, *Flat;
    cudaGetSymbolAddress((void**)&X0, g_X0);
    cudaGetSymbolAddress((void**)&H0p, g_H0p);
    cudaGetSymbolAddress((void**)&C1, g_C1);
    cudaGetSymbolAddress((void**)&X1, g_X1);
    cudaGetSymbolAddress((void**)&Flat, g_Flat);

    const int smem0 = (int)sizeof(MsgSmem<F0c, 16, 64>);
    const int smem1 = (int)sizeof(MsgSmem<F1c, 16, 64>);
    cudaFuncSetAttribute(msg_kernel<F0c, 16, 64>,
                         cudaFuncAttributeMaxDynamicSharedMemorySize, smem0);
    cudaFuncSetAttribute(msg_kernel<F1c, 16, 64>,
                         cudaFuncAttributeMaxDynamicSharedMemorySize, smem1);

    // layer 0 (gates fused into msg prologue; pool fused into gemm epilogue)
    msg_kernel<F0c, 16, 64><<<dim3(N0 / 16, BB), 256, smem0>>>(
        V, C, gkw0, gkb0, acw0, acb0, X0, N0);
    gemm_pool<N0><<<dim3(F1c / 64, BB * N0 / 128), 256>>>(
        X0, gcw0, gcb0, bng0, bnb0, H0p, (KK + 1) * F0c, F1c);
    poolC_kernel<<<(BB * N1 * 3 + 255) / 256, 256>>>(C, C1);

    // layer 1
    msg_kernel<F1c, 16, 64><<<dim3(N1 / 16, BB), 256, smem1>>>(
        H0p, C1, gkw1, gkb1, acw1, acb1, X1, N1);
    gemm_pool<N1><<<dim3(F2c / 64, BB * N1 / 128), 256>>>(
        X1, gcw1, gcb1, bng1, bnb1, Flat, (KK + 1) * F1c, F2c);

    // FC head
    fc_partial<<<64, 128>>>(Flat, fcw);
    fc_finalize<<<(BB * FC_OUT + 255) / 256, 256>>>(fcb, out);
}

// round 3
// speedup vs baseline: 2.0677x; 1.5317x over previous
#include <cuda_runtime.h>
#include <cstdint>

// ---------------- model constants ----------------
#define BB 16
#define N0 512
#define N1 256
#define N2 128
#define F0c 64
#define F1c 128
#define F2c 256
#define KK 8
#define FC_OUT 512
#define FLATD (N2 * F2c)        // 32768
#define EPSC 1e-9f

// ---------------- scratch (device globals, no allocs) ----------------
__device__ float g_X0[BB * N0 * (F0c + KK * F0c)];   // [8192, 576]
__device__ float g_H0p[BB * N1 * F1c];               // pooled layer-0 output
__device__ float g_C1[BB * N1 * 3];
__device__ float g_X1[BB * N1 * (F1c + KK * F1c)];   // [4096, 1152]
__device__ float g_Flat[BB * N2 * F2c];              // pooled layer-1 out = FC input
__device__ float g_part[64][BB * FC_OUT];            // split-K FC partials

// ---------------- tf32 helpers ----------------
__device__ __forceinline__ uint32_t f2tf(float x) {
    uint32_t r;
    asm("cvt.rna.tf32.f32 %0, %1;" : "=r"(r) : "f"(x));
    return r;
}
__device__ __forceinline__ void mma8(float* c,
        uint32_t a0, uint32_t a1, uint32_t a2, uint32_t a3,
        uint32_t b0, uint32_t b1) {
    asm volatile(
        "mma.sync.aligned.m16n8k8.row.col.f32.tf32.tf32.f32 "
        "{%0,%1,%2,%3},{%4,%5,%6,%7},{%8,%9},{%0,%1,%2,%3};"
        : "+f"(c[0]), "+f"(c[1]), "+f"(c[2]), "+f"(c[3])
        : "r"(a0), "r"(a1), "r"(a2), "r"(a3), "r"(b0), "r"(b1));
}

// =================================================================
// Fused message passing with tf32 tensor cores.
//   GEMM view per block: D[(k,i)=128 rows][F] = A'[128][N] x V[N][F]
//   A' built tile-by-tile in smem from coords + fused gates.
// =================================================================
template <int F, int N>
__global__ __launch_bounds__(256) void msg_kernel(
        const float* __restrict__ V, const float* __restrict__ C,
        const float* __restrict__ gkw, const float* __restrict__ gkb,
        const float* __restrict__ acw, const float* __restrict__ acb,
        float* __restrict__ X) {
    constexpr int TI = 16, TJ = 32, XW = F + KK * F;
    constexpr int WARPS_M = (F == 128) ? 2 : 4;
    constexpr int WARPS_N = 8 / WARPS_M;
    constexpr int WM = 128 / WARPS_M;       // 64 or 32
    constexpr int WN = F / WARPS_N;         // 32
    constexpr int TM = WM / 16;             // 4 or 2
    constexpr int TN = WN / 8;              // 4
    constexpr int VP = F + 8;               // V pitch (bank-conflict-free frags)

    __shared__ float4 sCi[TI];
    __shared__ float  sRni[TI];
    __shared__ float  sU[TI][KK];
    __shared__ float  sW[TI][KK];
    __shared__ float4 sCj[TJ];
    __shared__ float  sRnj[TJ];
    __shared__ uint32_t sA[128][36];        // A' tile, tf32 bits
    __shared__ uint32_t sV[TJ][VP];         // V tile, tf32 bits

    const int b = blockIdx.y;
    const int i0 = blockIdx.x * TI;
    const int tid = threadIdx.x;
    const int wid = tid >> 5, lane = tid & 31;
    const int g = lane >> 2, cc = lane & 3;
    const int warp_m = wid / WARPS_N, warp_n = wid % WARPS_N;

    // row-side coords
    if (tid < TI) {
        int i = i0 + tid;
        float x = C[((size_t)b * N + i) * 3 + 0];
        float y = C[((size_t)b * N + i) * 3 + 1];
        float z = C[((size_t)b * N + i) * 3 + 2];
        float l2 = x * x + y * y + z * z;
        sCi[tid] = make_float4(x, y, z, l2);
        sRni[tid] = rsqrtf(l2 + EPSC);
    }
    // fused gates: 256 threads = TI*KK*2
    {
        int gate = tid >> 7;
        int r = (tid >> 3) & (TI - 1);
        int k = tid & 7;
        const float* wgt = gate ? acw : gkw;
        float s = gate ? acb[k] : gkb[k];
        const float* vrow = V + ((size_t)b * N + i0 + r) * F;
#pragma unroll 8
        for (int f = 0; f < F; ++f) s += vrow[f] * wgt[f * KK + k];
        if (gate) sW[r][k] = 1.f / (1.f + __expf(-s));
        else      sU[r][k] = fmaxf(s, 0.f) + log1pf(__expf(-fabsf(s)));
    }
    // copy V rows into the first F columns of X (fp32 passthrough)
    for (int t = tid; t < TI * (F / 4); t += 256) {
        int i = t / (F / 4), fq = t % (F / 4);
        float4 vv = reinterpret_cast<const float4*>(V + ((size_t)b * N + i0 + i) * F)[fq];
        reinterpret_cast<float4*>(X + ((size_t)b * N + i0 + i) * XW)[fq] = vv;
    }

    float acc[TM][TN][4];
#pragma unroll
    for (int tm = 0; tm < TM; ++tm)
#pragma unroll
        for (int tn = 0; tn < TN; ++tn)
#pragma unroll
            for (int q = 0; q < 4; ++q) acc[tm][tn][q] = 0.f;

    for (int j0 = 0; j0 < N; j0 += TJ) {
        __syncthreads();   // prior-tile readers done (covers prologue on iter 0)
        if (tid < TJ) {
            int j = j0 + tid;
            float x = C[((size_t)b * N + j) * 3 + 0];
            float y = C[((size_t)b * N + j) * 3 + 1];
            float z = C[((size_t)b * N + j) * 3 + 2];
            float l2 = x * x + y * y + z * z;
            sCj[tid] = make_float4(x, y, z, l2);
            sRnj[tid] = rsqrtf(l2 + EPSC);
        }
        // V tile -> tf32 smem
        for (int t = tid; t < TJ * (F / 4); t += 256) {
            int j = t / (F / 4), fq = t % (F / 4);
            float4 vv = reinterpret_cast<const float4*>(
                V + ((size_t)b * N + j0 + j) * F)[fq];
            sV[j][fq * 4 + 0] = f2tf(vv.x);
            sV[j][fq * 4 + 1] = f2tf(vv.y);
            sV[j][fq * 4 + 2] = f2tf(vv.z);
            sV[j][fq * 4 + 3] = f2tf(vv.w);
        }
        __syncthreads();
        // build A' tile: rows (k*16+i), cols jj
#pragma unroll
        for (int s = 0; s < 2; ++s) {
            int p = tid + s * 256;
            int i = p >> 5, jj = p & 31;
            float4 ci = sCi[i], cj = sCj[jj];
            float dot = ci.x * cj.x + ci.y * cj.y + ci.z * cj.z;
            float d2 = fabsf(ci.w + cj.w - 2.f * dot) + EPSC;
            float cs = dot * sRni[i] * sRnj[jj];
#pragma unroll
            for (int k = 0; k < KK; ++k) {
                float e = __expf(-d2 * sU[i][k]);
                float wk = sW[i][k];
                sA[(k << 4) | i][jj] = f2tf(e * (wk * cs + 1.f - wk));
            }
        }
        __syncthreads();
        // mma: 4 k-steps of 8
#pragma unroll
        for (int ks = 0; ks < 4; ++ks) {
            uint32_t af[TM][4];
#pragma unroll
            for (int tm = 0; tm < TM; ++tm) {
                int r = warp_m * WM + tm * 16;
                af[tm][0] = sA[r + g][ks * 8 + cc];
                af[tm][1] = sA[r + g + 8][ks * 8 + cc];
                af[tm][2] = sA[r + g][ks * 8 + cc + 4];
                af[tm][3] = sA[r + g + 8][ks * 8 + cc + 4];
            }
#pragma unroll
            for (int tn = 0; tn < TN; ++tn) {
                int nb = warp_n * WN + tn * 8;
                uint32_t b0 = sV[ks * 8 + cc][nb + g];
                uint32_t b1 = sV[ks * 8 + cc + 4][nb + g];
#pragma unroll
                for (int tm = 0; tm < TM; ++tm)
                    mma8(acc[tm][tn], af[tm][0], af[tm][1], af[tm][2], af[tm][3], b0, b1);
            }
        }
    }

    // write M section of X: row m = k*16+i
#pragma unroll
    for (int tm = 0; tm < TM; ++tm) {
#pragma unroll
        for (int half = 0; half < 2; ++half) {
            int m = warp_m * WM + tm * 16 + g + half * 8;
            int k = m >> 4, i = m & 15;
            float* xr = X + ((size_t)b * N + i0 + i) * XW + F + k * F + warp_n * WN;
#pragma unroll
            for (int tn = 0; tn < TN; ++tn) {
                float2 o;
                o.x = acc[tm][tn][half * 2 + 0];
                o.y = acc[tm][tn][half * 2 + 1];
                *reinterpret_cast<float2*>(xr + tn * 8 + 2 * cc) = o;
            }
        }
    }
}

// =================================================================
// tf32 GEMM + tanh + BN affine + fused 2:1 row pooling (shuffle)
// =================================================================
template <int NIN>
__global__ __launch_bounds__(256) void gemm_pool(
        const float* __restrict__ A, const float* __restrict__ Wt,
        const float* __restrict__ bias, const float* __restrict__ bng,
        const float* __restrict__ bnb, float* __restrict__ Out,
        int Kd, int Nc) {
    constexpr int BM = 128, BN = 64, BK = 32;
    constexpr int TM = 2, TN = 4;                // warps 4(M) x 2(N), WM=32, WN=32
    __shared__ uint32_t As[BM][BK + 4];          // pitch 36
    __shared__ uint32_t Bs[BK][BN + 8];          // pitch 72
    const int bm = blockIdx.y * BM, bn = blockIdx.x * BN;
    const int tid = threadIdx.x, wid = tid >> 5, lane = tid & 31;
    const int g = lane >> 2, cc = lane & 3;
    const int warp_m = wid >> 1, warp_n = wid & 1;

    float acc[TM][TN][4];
#pragma unroll
    for (int tm = 0; tm < TM; ++tm)
#pragma unroll
        for (int tn = 0; tn < TN; ++tn)
#pragma unroll
            for (int q = 0; q < 4; ++q) acc[tm][tn][q] = 0.f;

    float4 ra[4], rb[2];
    const int nk = Kd / BK;

    // A loader: 128x32 floats = 1024 float4, 4/thread: r=idx>>3, cq=idx&7
    // B loader: 32x64 floats  = 512 float4,  2/thread: kr=idx>>4, cq=idx&15
    {
#pragma unroll
        for (int s = 0; s < 4; ++s) {
            int idx = tid + s * 256, r = idx >> 3, cq = idx & 7;
            ra[s] = *reinterpret_cast<const float4*>(A + (size_t)(bm + r) * Kd + cq * 4);
        }
#pragma unroll
        for (int s = 0; s < 2; ++s) {
            int idx = tid + s * 256, kr = idx >> 4, cq = idx & 15;
            rb[s] = *reinterpret_cast<const float4*>(Wt + (size_t)kr * Nc + bn + cq * 4);
        }
    }

    for (int kt = 0; kt < nk; ++kt) {
        // stage regs -> smem (tf32 convert)
#pragma unroll
        for (int s = 0; s < 4; ++s) {
            int idx = tid + s * 256, r = idx >> 3, cq = idx & 7;
            As[r][cq * 4 + 0] = f2tf(ra[s].x);
            As[r][cq * 4 + 1] = f2tf(ra[s].y);
            As[r][cq * 4 + 2] = f2tf(ra[s].z);
            As[r][cq * 4 + 3] = f2tf(ra[s].w);
        }
#pragma unroll
        for (int s = 0; s < 2; ++s) {
            int idx = tid + s * 256, kr = idx >> 4, cq = idx & 15;
            Bs[kr][cq * 4 + 0] = f2tf(rb[s].x);
            Bs[kr][cq * 4 + 1] = f2tf(rb[s].y);
            Bs[kr][cq * 4 + 2] = f2tf(rb[s].z);
            Bs[kr][cq * 4 + 3] = f2tf(rb[s].w);
        }
        __syncthreads();
        if (kt + 1 < nk) {
            int k0 = (kt + 1) * BK;
#pragma unroll
            for (int s = 0; s < 4; ++s) {
                int idx = tid + s * 256, r = idx >> 3, cq = idx & 7;
                ra[s] = *reinterpret_cast<const float4*>(
                    A + (size_t)(bm + r) * Kd + k0 + cq * 4);
            }
#pragma unroll
            for (int s = 0; s < 2; ++s) {
                int idx = tid + s * 256, kr = idx >> 4, cq = idx & 15;
                rb[s] = *reinterpret_cast<const float4*>(
                    Wt + (size_t)(k0 + kr) * Nc + bn + cq * 4);
            }
        }
#pragma unroll
        for (int ks = 0; ks < 4; ++ks) {
            uint32_t af[TM][4];
#pragma unroll
            for (int tm = 0; tm < TM; ++tm) {
                int r = warp_m * 32 + tm * 16;
                af[tm][0] = As[r + g][ks * 8 + cc];
                af[tm][1] = As[r + g + 8][ks * 8 + cc];
                af[tm][2] = As[r + g][ks * 8 + cc + 4];
                af[tm][3] = As[r + g + 8][ks * 8 + cc + 4];
            }
#pragma unroll
            for (int tn = 0; tn < TN; ++tn) {
                int nb = warp_n * 32 + tn * 8;
                uint32_t b0 = Bs[ks * 8 + cc][nb + g];
                uint32_t b1 = Bs[ks * 8 + cc + 4][nb + g];
#pragma unroll
                for (int tm = 0; tm < TM; ++tm)
                    mma8(acc[tm][tn], af[tm][0], af[tm][1], af[tm][2], af[tm][3], b0, b1);
            }
        }
        __syncthreads();
    }

    // epilogue: tanh + BN + pool rows (2r, 2r+1) via shuffle (row+1 lives in lane+4)
    const bool wr = ((g & 1) == 0);
#pragma unroll
    for (int tm = 0; tm < TM; ++tm) {
#pragma unroll
        for (int half = 0; half < 2; ++half) {
            int r = bm + warp_m * 32 + tm * 16 + g + half * 8;
#pragma unroll
            for (int tn = 0; tn < TN; ++tn) {
                int col = bn + warp_n * 32 + tn * 8 + 2 * cc;
                float h0 = bng[col] * tanhf(acc[tm][tn][half * 2 + 0] + bias[col]) + bnb[col];
                float h1 = bng[col + 1] * tanhf(acc[tm][tn][half * 2 + 1] + bias[col + 1]) + bnb[col + 1];
                float p0 = 0.5f * (h0 + __shfl_down_sync(0xffffffffu, h0, 4));
                float p1 = 0.5f * (h1 + __shfl_down_sync(0xffffffffu, h1, 4));
                if (wr) {
                    int pr = (r / NIN) * (NIN / 2) + (r % NIN) / 2;
                    *reinterpret_cast<float2*>(Out + (size_t)pr * Nc + col) =
                        make_float2(p0, p1);
                }
            }
        }
    }
}

// ---------------- coord pooling (tiny) ----------------
__global__ void poolC_kernel(const float* __restrict__ C, float* __restrict__ C1) {
    int idx = blockIdx.x * blockDim.x + threadIdx.x;
    if (idx >= BB * N1 * 3) return;
    int c = idx % 3;
    int i = (idx / 3) % N1;
    int b = idx / (3 * N1);
    size_t base = ((size_t)b * N0 + 2 * i) * 3 + c;
    C1[idx] = 0.5f * (C[base] + C[base + 3]);
}

// ---------------- FC: split-K partials (fp32, deterministic) ----------------
__global__ __launch_bounds__(128) void fc_partial(const float* __restrict__ Flat,
                                                  const float* __restrict__ W) {
    constexpr int KCH = FLATD / 64;   // 512
    const int kb = blockIdx.x * KCH;
    const int tid = threadIdx.x;
    __shared__ float sF[BB][KCH];
    for (int t = tid; t < BB * KCH / 4; t += 128) {
        int b = t / (KCH / 4), kq = t % (KCH / 4);
        *reinterpret_cast<float4*>(&sF[b][kq * 4]) =
            *reinterpret_cast<const float4*>(Flat + (size_t)b * FLATD + kb + kq * 4);
    }
    __syncthreads();

    float4 acc[BB];
#pragma unroll
    for (int b = 0; b < BB; ++b) acc[b] = make_float4(0.f, 0.f, 0.f, 0.f);

    const float* wp = W + (size_t)kb * FC_OUT + tid * 4;
    for (int k = 0; k < KCH; k += 4) {
        float4 w0 = *reinterpret_cast<const float4*>(wp + (size_t)(k + 0) * FC_OUT);
        float4 w1 = *reinterpret_cast<const float4*>(wp + (size_t)(k + 1) * FC_OUT);
        float4 w2 = *reinterpret_cast<const float4*>(wp + (size_t)(k + 2) * FC_OUT);
        float4 w3 = *reinterpret_cast<const float4*>(wp + (size_t)(k + 3) * FC_OUT);
#pragma unroll
        for (int b = 0; b < BB; ++b) {
            float4 f = *reinterpret_cast<float4*>(&sF[b][k]);
            acc[b].x += f.x * w0.x + f.y * w1.x + f.z * w2.x + f.w * w3.x;
            acc[b].y += f.x * w0.y + f.y * w1.y + f.z * w2.y + f.w * w3.y;
            acc[b].z += f.x * w0.z + f.y * w1.z + f.z * w2.z + f.w * w3.z;
            acc[b].w += f.x * w0.w + f.y * w1.w + f.z * w2.w + f.w * w3.w;
        }
    }
#pragma unroll
    for (int b = 0; b < BB; ++b)
        *reinterpret_cast<float4*>(&g_part[blockIdx.x][b * FC_OUT + tid * 4]) = acc[b];
}

__global__ void fc_finalize(const float* __restrict__ fcb, float* __restrict__ out) {
    int idx = blockIdx.x * blockDim.x + threadIdx.x;
    if (idx >= BB * FC_OUT) return;
    int col = idx & (FC_OUT - 1);
    float s = fcb[col];
#pragma unroll
    for (int t = 0; t < 64; ++t) s += g_part[t][idx];
    out[idx] = 1.f / (1.f + __expf(-s));
}

// ---------------- launch ----------------
extern "C" void kernel_launch(void* const* d_in, const int* in_sizes, int n_in,
                              void* d_out, int out_size) {
    const float* V    = (const float*)d_in[0];
    const float* C    = (const float*)d_in[1];
    const float* gkw0 = (const float*)d_in[2];
    const float* gkb0 = (const float*)d_in[3];
    const float* acw0 = (const float*)d_in[4];
    const float* acb0 = (const float*)d_in[5];
    const float* gcw0 = (const float*)d_in[6];
    const float* gcb0 = (const float*)d_in[7];
    const float* bng0 = (const float*)d_in[8];
    const float* bnb0 = (const float*)d_in[9];
    const float* gkw1 = (const float*)d_in[10];
    const float* gkb1 = (const float*)d_in[11];
    const float* acw1 = (const float*)d_in[12];
    const float* acb1 = (const float*)d_in[13];
    const float* gcw1 = (const float*)d_in[14];
    const float* gcb1 = (const float*)d_in[15];
    const float* bng1 = (const float*)d_in[16];
    const float* bnb1 = (const float*)d_in[17];
    const float* fcw  = (const float*)d_in[18];
    const float* fcb  = (const float*)d_in[19];
    float* out = (float*)d_out;

    float *X0, *H0p, *C1, *X1, *Flat;
    cudaGetSymbolAddress((void**)&X0, g_X0);
    cudaGetSymbolAddress((void**)&H0p, g_H0p);
    cudaGetSymbolAddress((void**)&C1, g_C1);
    cudaGetSymbolAddress((void**)&X1, g_X1);
    cudaGetSymbolAddress((void**)&Flat, g_Flat);

    // layer 0
    msg_kernel<F0c, N0><<<dim3(N0 / 16, BB), 256>>>(
        V, C, gkw0, gkb0, acw0, acb0, X0);
    gemm_pool<N0><<<dim3(F1c / 64, BB * N0 / 128), 256>>>(
        X0, gcw0, gcb0, bng0, bnb0, H0p, (KK + 1) * F0c, F1c);
    poolC_kernel<<<(BB * N1 * 3 + 255) / 256, 256>>>(C, C1);

    // layer 1
    msg_kernel<F1c, N1><<<dim3(N1 / 16, BB), 256>>>(
        H0p, C1, gkw1, gkb1, acw1, acb1, X1);
    gemm_pool<N1><<<dim3(F2c / 64, BB * N1 / 128), 256>>>(
        X1, gcw1, gcb1, bng1, bnb1, Flat, (KK + 1) * F1c, F2c);

    // FC head (fp32)
    fc_partial<<<64, 128>>>(Flat, fcw);
    fc_finalize<<<(BB * FC_OUT + 255) / 256, 256>>>(fcb, out);
}

// round 4
// speedup vs baseline: 2.4560x; 1.1878x over previous
#include <cuda_runtime.h>
#include <cstdint>

// ---------------- model constants ----------------
#define BB 16
#define N0 512
#define N1 256
#define N2 128
#define F0c 64
#define F1c 128
#define F2c 256
#define KK 8
#define FC_OUT 512
#define FLATD (N2 * F2c)        // 32768
#define EPSC 1e-9f
#define ZCUT 40.0f              // exp(-z) below this is numerically zero vs tol

// ---------------- scratch (device globals, no allocs) ----------------
__device__ float g_X0[BB * N0 * (F0c + KK * F0c)];   // [8192, 576]
__device__ float g_H0p[BB * N1 * F1c];               // pooled layer-0 output
__device__ float g_C1[BB * N1 * 3];
__device__ float g_X1[BB * N1 * (F1c + KK * F1c)];   // [4096, 1152]
__device__ float g_Flat[BB * N2 * F2c];              // pooled layer-1 out = FC input
__device__ float g_part[128][BB * FC_OUT];           // split-K FC partials

// ---------------- tf32 helpers ----------------
__device__ __forceinline__ uint32_t f2tf(float x) {
    uint32_t r;
    asm("cvt.rna.tf32.f32 %0, %1;" : "=r"(r) : "f"(x));
    return r;
}
__device__ __forceinline__ void mma8(float* c,
        uint32_t a0, uint32_t a1, uint32_t a2, uint32_t a3,
        uint32_t b0, uint32_t b1) {
    asm volatile(
        "mma.sync.aligned.m16n8k8.row.col.f32.tf32.tf32.f32 "
        "{%0,%1,%2,%3},{%4,%5,%6,%7},{%8,%9},{%0,%1,%2,%3};"
        : "+f"(c[0]), "+f"(c[1]), "+f"(c[2]), "+f"(c[3])
        : "r"(a0), "r"(a1), "r"(a2), "r"(a3), "r"(b0), "r"(b1));
}

// =================================================================
// Fused message passing, tf32 tensor cores, exp-sparsified A build.
//   Per block: D[(k,i)=128 rows][F] = A'[128][N] x V[N][F]
//   A' tile built with far-pair short-circuit (A=0) + compacted exp list.
// =================================================================
template <int F, int N>
__global__ __launch_bounds__(256) void msg_kernel(
        const float* __restrict__ V, const float* __restrict__ C,
        const float* __restrict__ gkw, const float* __restrict__ gkb,
        const float* __restrict__ acw, const float* __restrict__ acb,
        float* __restrict__ X) {
    constexpr int TI = 16, TJ = 32, XW = F + KK * F;
    constexpr int WARPS_M = (F == 128) ? 2 : 4;
    constexpr int WARPS_N = 8 / WARPS_M;
    constexpr int WM = 128 / WARPS_M;
    constexpr int WN = F / WARPS_N;         // 32
    constexpr int TM = WM / 16;
    constexpr int TN = WN / 8;              // 4
    constexpr int VP = F + 8;

    __shared__ float4 sCi[TI];
    __shared__ float  sRni[TI];
    __shared__ float  sU[TI][KK];
    __shared__ float  sW[TI][KK];
    __shared__ float  sUmin[TI];
    __shared__ float4 sCj[TJ];
    __shared__ float  sRnj[TJ];
    __shared__ uint32_t sA[128][36];
    __shared__ uint32_t sV[TJ][VP];
    __shared__ int sCnt;
    __shared__ unsigned short cIdx[TI * TJ];
    __shared__ float cD2[TI * TJ];
    __shared__ float cCs[TI * TJ];

    const int b = blockIdx.y;
    const int i0 = blockIdx.x * TI;
    const int tid = threadIdx.x;
    const int wid = tid >> 5, lane = tid & 31;
    const int g = lane >> 2, cc = lane & 3;
    const int warp_m = wid / WARPS_N, warp_n = wid % WARPS_N;

    // row-side coords
    if (tid < TI) {
        int i = i0 + tid;
        float x = C[((size_t)b * N + i) * 3 + 0];
        float y = C[((size_t)b * N + i) * 3 + 1];
        float z = C[((size_t)b * N + i) * 3 + 2];
        float l2 = x * x + y * y + z * z;
        sCi[tid] = make_float4(x, y, z, l2);
        sRni[tid] = rsqrtf(l2 + EPSC);
    }
    // fused gates: 256 threads = TI*KK*2
    {
        int gate = tid >> 7;
        int r = (tid >> 3) & (TI - 1);
        int k = tid & 7;
        const float* wgt = gate ? acw : gkw;
        float s = gate ? acb[k] : gkb[k];
        const float* vrow = V + ((size_t)b * N + i0 + r) * F;
#pragma unroll 8
        for (int f = 0; f < F; ++f) s += vrow[f] * wgt[f * KK + k];
        if (gate) sW[r][k] = 1.f / (1.f + __expf(-s));
        else      sU[r][k] = fmaxf(s, 0.f) + log1pf(__expf(-fabsf(s)));
    }
    // copy V rows into the first F columns of X
    for (int t = tid; t < TI * (F / 4); t += 256) {
        int i = t / (F / 4), fq = t % (F / 4);
        float4 vv = reinterpret_cast<const float4*>(V + ((size_t)b * N + i0 + i) * F)[fq];
        reinterpret_cast<float4*>(X + ((size_t)b * N + i0 + i) * XW)[fq] = vv;
    }
    __syncthreads();
    if (tid < TI) {   // per-row min_k u
        float m = sU[tid][0];
#pragma unroll
        for (int k = 1; k < KK; ++k) m = fminf(m, sU[tid][k]);
        sUmin[tid] = m;
    }

    float acc[TM][TN][4];
#pragma unroll
    for (int tm = 0; tm < TM; ++tm)
#pragma unroll
        for (int tn = 0; tn < TN; ++tn)
#pragma unroll
            for (int q = 0; q < 4; ++q) acc[tm][tn][q] = 0.f;

    for (int j0 = 0; j0 < N; j0 += TJ) {
        __syncthreads();   // prior-tile readers done; sUmin visible on iter 0
        if (tid < TJ) {
            int j = j0 + tid;
            float x = C[((size_t)b * N + j) * 3 + 0];
            float y = C[((size_t)b * N + j) * 3 + 1];
            float z = C[((size_t)b * N + j) * 3 + 2];
            float l2 = x * x + y * y + z * z;
            sCj[tid] = make_float4(x, y, z, l2);
            sRnj[tid] = rsqrtf(l2 + EPSC);
        }
        for (int t = tid; t < TJ * (F / 4); t += 256) {
            int j = t / (F / 4), fq = t % (F / 4);
            float4 vv = reinterpret_cast<const float4*>(
                V + ((size_t)b * N + j0 + j) * F)[fq];
            sV[j][fq * 4 + 0] = f2tf(vv.x);
            sV[j][fq * 4 + 1] = f2tf(vv.y);
            sV[j][fq * 4 + 2] = f2tf(vv.z);
            sV[j][fq * 4 + 3] = f2tf(vv.w);
        }
        if (tid == 0) sCnt = 0;
        __syncthreads();
        // phase 1: distance test, zero far pairs, compact near pairs
#pragma unroll
        for (int s = 0; s < 2; ++s) {
            int p = tid + s * 256;
            int i = p >> 5, jj = p & 31;
            float4 ci = sCi[i], cj = sCj[jj];
            float dot = ci.x * cj.x + ci.y * cj.y + ci.z * cj.z;
            float d2 = fabsf(ci.w + cj.w - 2.f * dot) + EPSC;
            if (d2 * sUmin[i] > ZCUT) {
#pragma unroll
                for (int k = 0; k < KK; ++k) sA[(k << 4) | i][jj] = 0u;
            } else {
                float cs = dot * sRni[i] * sRnj[jj];
                int slot = atomicAdd(&sCnt, 1);
                cIdx[slot] = (unsigned short)p;
                cD2[slot] = d2;
                cCs[slot] = cs;
            }
        }
        __syncthreads();
        // phase 2: dense exp work over compacted list (entry x k)
        const int work = sCnt * KK;
        for (int t = tid; t < work; t += 256) {
            int e = t >> 3, k = t & 7;
            int p = cIdx[e];
            int i = p >> 5, jj = p & 31;
            float d2 = cD2[e], cs = cCs[e];
            float u = sU[i][k], w = sW[i][k];
            float z = d2 * u;
            float ex = (z > ZCUT) ? 0.f : __expf(-z);
            sA[(k << 4) | i][jj] = f2tf(ex * (w * cs + 1.f - w));
        }
        __syncthreads();
        // mma: 4 k-steps of 8
#pragma unroll
        for (int ks = 0; ks < 4; ++ks) {
            uint32_t af[TM][4];
#pragma unroll
            for (int tm = 0; tm < TM; ++tm) {
                int r = warp_m * WM + tm * 16;
                af[tm][0] = sA[r + g][ks * 8 + cc];
                af[tm][1] = sA[r + g + 8][ks * 8 + cc];
                af[tm][2] = sA[r + g][ks * 8 + cc + 4];
                af[tm][3] = sA[r + g + 8][ks * 8 + cc + 4];
            }
#pragma unroll
            for (int tn = 0; tn < TN; ++tn) {
                int nb = warp_n * WN + tn * 8;
                uint32_t b0 = sV[ks * 8 + cc][nb + g];
                uint32_t b1 = sV[ks * 8 + cc + 4][nb + g];
#pragma unroll
                for (int tm = 0; tm < TM; ++tm)
                    mma8(acc[tm][tn], af[tm][0], af[tm][1], af[tm][2], af[tm][3], b0, b1);
            }
        }
    }

    // write M section of X: row m = k*16+i
#pragma unroll
    for (int tm = 0; tm < TM; ++tm) {
#pragma unroll
        for (int half = 0; half < 2; ++half) {
            int m = warp_m * WM + tm * 16 + g + half * 8;
            int k = m >> 4, i = m & 15;
            float* xr = X + ((size_t)b * N + i0 + i) * XW + F + k * F + warp_n * WN;
#pragma unroll
            for (int tn = 0; tn < TN; ++tn) {
                float2 o;
                o.x = acc[tm][tn][half * 2 + 0];
                o.y = acc[tm][tn][half * 2 + 1];
                *reinterpret_cast<float2*>(xr + tn * 8 + 2 * cc) = o;
            }
        }
    }
}

// =================================================================
// tf32 GEMM + tanh + BN affine + fused 2:1 row pooling (shuffle)
// =================================================================
template <int NIN>
__global__ __launch_bounds__(256) void gemm_pool(
        const float* __restrict__ A, const float* __restrict__ Wt,
        const float* __restrict__ bias, const float* __restrict__ bng,
        const float* __restrict__ bnb, float* __restrict__ Out,
        int Kd, int Nc) {
    constexpr int BM = 128, BN = 64, BK = 32;
    constexpr int TM = 2, TN = 4;                // warps 4(M) x 2(N)
    __shared__ uint32_t As[BM][BK + 4];
    __shared__ uint32_t Bs[BK][BN + 8];
    const int bm = blockIdx.y * BM, bn = blockIdx.x * BN;
    const int tid = threadIdx.x, wid = tid >> 5, lane = tid & 31;
    const int g = lane >> 2, cc = lane & 3;
    const int warp_m = wid >> 1, warp_n = wid & 1;

    float acc[TM][TN][4];
#pragma unroll
    for (int tm = 0; tm < TM; ++tm)
#pragma unroll
        for (int tn = 0; tn < TN; ++tn)
#pragma unroll
            for (int q = 0; q < 4; ++q) acc[tm][tn][q] = 0.f;

    float4 ra[4], rb[2];
    const int nk = Kd / BK;

    {
#pragma unroll
        for (int s = 0; s < 4; ++s) {
            int idx = tid + s * 256, r = idx >> 3, cq = idx & 7;
            ra[s] = *reinterpret_cast<const float4*>(A + (size_t)(bm + r) * Kd + cq * 4);
        }
#pragma unroll
        for (int s = 0; s < 2; ++s) {
            int idx = tid + s * 256, kr = idx >> 4, cq = idx & 15;
            rb[s] = *reinterpret_cast<const float4*>(Wt + (size_t)kr * Nc + bn + cq * 4);
        }
    }

    for (int kt = 0; kt < nk; ++kt) {
#pragma unroll
        for (int s = 0; s < 4; ++s) {
            int idx = tid + s * 256, r = idx >> 3, cq = idx & 7;
            As[r][cq * 4 + 0] = f2tf(ra[s].x);
            As[r][cq * 4 + 1] = f2tf(ra[s].y);
            As[r][cq * 4 + 2] = f2tf(ra[s].z);
            As[r][cq * 4 + 3] = f2tf(ra[s].w);
        }
#pragma unroll
        for (int s = 0; s < 2; ++s) {
            int idx = tid + s * 256, kr = idx >> 4, cq = idx & 15;
            Bs[kr][cq * 4 + 0] = f2tf(rb[s].x);
            Bs[kr][cq * 4 + 1] = f2tf(rb[s].y);
            Bs[kr][cq * 4 + 2] = f2tf(rb[s].z);
            Bs[kr][cq * 4 + 3] = f2tf(rb[s].w);
        }
        __syncthreads();
        if (kt + 1 < nk) {
            int k0 = (kt + 1) * BK;
#pragma unroll
            for (int s = 0; s < 4; ++s) {
                int idx = tid + s * 256, r = idx >> 3, cq = idx & 7;
                ra[s] = *reinterpret_cast<const float4*>(
                    A + (size_t)(bm + r) * Kd + k0 + cq * 4);
            }
#pragma unroll
            for (int s = 0; s < 2; ++s) {
                int idx = tid + s * 256, kr = idx >> 4, cq = idx & 15;
                rb[s] = *reinterpret_cast<const float4*>(
                    Wt + (size_t)(k0 + kr) * Nc + bn + cq * 4);
            }
        }
#pragma unroll
        for (int ks = 0; ks < 4; ++ks) {
            uint32_t af[TM][4];
#pragma unroll
            for (int tm = 0; tm < TM; ++tm) {
                int r = warp_m * 32 + tm * 16;
                af[tm][0] = As[r + g][ks * 8 + cc];
                af[tm][1] = As[r + g + 8][ks * 8 + cc];
                af[tm][2] = As[r + g][ks * 8 + cc + 4];
                af[tm][3] = As[r + g + 8][ks * 8 + cc + 4];
            }
#pragma unroll
            for (int tn = 0; tn < TN; ++tn) {
                int nb = warp_n * 32 + tn * 8;
                uint32_t b0 = Bs[ks * 8 + cc][nb + g];
                uint32_t b1 = Bs[ks * 8 + cc + 4][nb + g];
#pragma unroll
                for (int tm = 0; tm < TM; ++tm)
                    mma8(acc[tm][tn], af[tm][0], af[tm][1], af[tm][2], af[tm][3], b0, b1);
            }
        }
        __syncthreads();
    }

    const bool wr = ((g & 1) == 0);
#pragma unroll
    for (int tm = 0; tm < TM; ++tm) {
#pragma unroll
        for (int half = 0; half < 2; ++half) {
            int r = bm + warp_m * 32 + tm * 16 + g + half * 8;
#pragma unroll
            for (int tn = 0; tn < TN; ++tn) {
                int col = bn + warp_n * 32 + tn * 8 + 2 * cc;
                float h0 = bng[col] * tanhf(acc[tm][tn][half * 2 + 0] + bias[col]) + bnb[col];
                float h1 = bng[col + 1] * tanhf(acc[tm][tn][half * 2 + 1] + bias[col + 1]) + bnb[col + 1];
                float p0 = 0.5f * (h0 + __shfl_down_sync(0xffffffffu, h0, 4));
                float p1 = 0.5f * (h1 + __shfl_down_sync(0xffffffffu, h1, 4));
                if (wr) {
                    int pr = (r / NIN) * (NIN / 2) + (r % NIN) / 2;
                    *reinterpret_cast<float2*>(Out + (size_t)pr * Nc + col) =
                        make_float2(p0, p1);
                }
            }
        }
    }
}

// ---------------- coord pooling (tiny) ----------------
__global__ void poolC_kernel(const float* __restrict__ C, float* __restrict__ C1) {
    int idx = blockIdx.x * blockDim.x + threadIdx.x;
    if (idx >= BB * N1 * 3) return;
    int c = idx % 3;
    int i = (idx / 3) % N1;
    int b = idx / (3 * N1);
    size_t base = ((size_t)b * N0 + 2 * i) * 3 + c;
    C1[idx] = 0.5f * (C[base] + C[base + 3]);
}

// ---------------- FC: split-K partials (fp32, deterministic) ----------------
__global__ __launch_bounds__(128) void fc_partial(const float* __restrict__ Flat,
                                                  const float* __restrict__ W) {
    constexpr int KCH = FLATD / 128;   // 256
    const int kb = blockIdx.x * KCH;
    const int tid = threadIdx.x;
    __shared__ float sF[BB][KCH];      // 16KB
    for (int t = tid; t < BB * KCH / 4; t += 128) {
        int b = t / (KCH / 4), kq = t % (KCH / 4);
        *reinterpret_cast<float4*>(&sF[b][kq * 4]) =
            *reinterpret_cast<const float4*>(Flat + (size_t)b * FLATD + kb + kq * 4);
    }
    __syncthreads();

    float4 acc[BB];
#pragma unroll
    for (int b = 0; b < BB; ++b) acc[b] = make_float4(0.f, 0.f, 0.f, 0.f);

    const float* wp = W + (size_t)kb * FC_OUT + tid * 4;
    for (int k = 0; k < KCH; k += 4) {
        float4 w0 = *reinterpret_cast<const float4*>(wp + (size_t)(k + 0) * FC_OUT);
        float4 w1 = *reinterpret_cast<const float4*>(wp + (size_t)(k + 1) * FC_OUT);
        float4 w2 = *reinterpret_cast<const float4*>(wp + (size_t)(k + 2) * FC_OUT);
        float4 w3 = *reinterpret_cast<const float4*>(wp + (size_t)(k + 3) * FC_OUT);
#pragma unroll
        for (int b = 0; b < BB; ++b) {
            float4 f = *reinterpret_cast<float4*>(&sF[b][k]);
            acc[b].x += f.x * w0.x + f.y * w1.x + f.z * w2.x + f.w * w3.x;
            acc[b].y += f.x * w0.y + f.y * w1.y + f.z * w2.y + f.w * w3.y;
            acc[b].z += f.x * w0.z + f.y * w1.z + f.z * w2.z + f.w * w3.z;
            acc[b].w += f.x * w0.w + f.y * w1.w + f.z * w2.w + f.w * w3.w;
        }
    }
#pragma unroll
    for (int b = 0; b < BB; ++b)
        *reinterpret_cast<float4*>(&g_part[blockIdx.x][b * FC_OUT + tid * 4]) = acc[b];
}

__global__ void fc_finalize(const float* __restrict__ fcb, float* __restrict__ out) {
    int idx = blockIdx.x * blockDim.x + threadIdx.x;
    if (idx >= BB * FC_OUT) return;
    int col = idx & (FC_OUT - 1);
    float s = fcb[col];
#pragma unroll
    for (int t = 0; t < 128; ++t) s += g_part[t][idx];
    out[idx] = 1.f / (1.f + __expf(-s));
}

// ---------------- launch ----------------
extern "C" void kernel_launch(void* const* d_in, const int* in_sizes, int n_in,
                              void* d_out, int out_size) {
    const float* V    = (const float*)d_in[0];
    const float* C    = (const float*)d_in[1];
    const float* gkw0 = (const float*)d_in[2];
    const float* gkb0 = (const float*)d_in[3];
    const float* acw0 = (const float*)d_in[4];
    const float* acb0 = (const float*)d_in[5];
    const float* gcw0 = (const float*)d_in[6];
    const float* gcb0 = (const float*)d_in[7];
    const float* bng0 = (const float*)d_in[8];
    const float* bnb0 = (const float*)d_in[9];
    const float* gkw1 = (const float*)d_in[10];
    const float* gkb1 = (const float*)d_in[11];
    const float* acw1 = (const float*)d_in[12];
    const float* acb1 = (const float*)d_in[13];
    const float* gcw1 = (const float*)d_in[14];
    const float* gcb1 = (const float*)d_in[15];
    const float* bng1 = (const float*)d_in[16];
    const float* bnb1 = (const float*)d_in[17];
    const float* fcw  = (const float*)d_in[18];
    const float* fcb  = (const float*)d_in[19];
    float* out = (float*)d_out;

    float *X0, *H0p, *C1, *X1, *Flat;
    cudaGetSymbolAddress((void**)&X0, g_X0);
    cudaGetSymbolAddress((void**)&H0p, g_H0p);
    cudaGetSymbolAddress((void**)&C1, g_C1);
    cudaGetSymbolAddress((void**)&X1, g_X1);
    cudaGetSymbolAddress((void**)&Flat, g_Flat);

    // layer 0
    msg_kernel<F0c, N0><<<dim3(N0 / 16, BB), 256>>>(
        V, C, gkw0, gkb0, acw0, acb0, X0);
    gemm_pool<N0><<<dim3(F1c / 64, BB * N0 / 128), 256>>>(
        X0, gcw0, gcb0, bng0, bnb0, H0p, (KK + 1) * F0c, F1c);
    poolC_kernel<<<(BB * N1 * 3 + 255) / 256, 256>>>(C, C1);

    // layer 1
    msg_kernel<F1c, N1><<<dim3(N1 / 16, BB), 256>>>(
        H0p, C1, gkw1, gkb1, acw1, acb1, X1);
    gemm_pool<N1><<<dim3(F2c / 64, BB * N1 / 128), 256>>>(
        X1, gcw1, gcb1, bng1, bnb1, Flat, (KK + 1) * F1c, F2c);

    // FC head (fp32)
    fc_partial<<<128, 128>>>(Flat, fcw);
    fc_finalize<<<(BB * FC_OUT + 255) / 256, 256>>>(fcb, out);
}